// round 5
// baseline (speedup 1.0000x reference)
#include <cuda_runtime.h>
#include <cuda_bf16.h>
#include <math_constants.h>
#include <cstdint>

// Problem constants
#define N_ROWS   65536
#define EMB_DIM  64
#define N_CODES  8192
#define NZ_ELEMS 4194304
#define BETA     0.25f

// Phase A (tensor filter) config
#define ROWS_PER_CTA 128
#define A_CTAS   (N_ROWS / ROWS_PER_CTA)    // 512
#define CT       256                         // codes per smem tile
#define NT       (N_CODES / CT)              // 32
#define TILE_B   32768                       // 256 codes * 64 k * 2B, frag-packed
#define MARGIN   1.5e-4f
#define CAP      32

#define LB       1024                        // loss partial blocks (64 rows each)

// ---------------- device scratch (no cudaMalloc allowed) -------------------
__device__ float g_enorm[N_CODES];
__device__ __align__(16) __nv_bfloat16 g_embB[N_CODES * EMB_DIM]; // frag-packed
__device__ int   g_idx_buf[N_ROWS];
__device__ float g_partials[LB];
__device__ int   g_cand[(size_t)N_ROWS * 4 * CAP];
__device__ int   g_ccnt[N_ROWS * 4];

// ---------------- helpers ---------------------------------------------------
__device__ __forceinline__ uint32_t smem_u32(const void* p) {
    uint32_t a;
    asm("{ .reg .u64 t; cvta.to.shared.u64 t, %1; cvt.u32.u64 %0, t; }"
        : "=r"(a) : "l"(p));
    return a;
}
__device__ __forceinline__ void cp_async16(uint32_t sm, const void* g) {
    asm volatile("cp.async.cg.shared.global [%0], [%1], 16;" :: "r"(sm), "l"(g));
}
#define CP_COMMIT() asm volatile("cp.async.commit_group;")
#define CP_WAIT1()  asm volatile("cp.async.wait_group 1;")

__device__ __forceinline__ uint32_t pack_bf2(float x, float y) {
    __nv_bfloat162 h = __floats2bfloat162_rn(x, y);   // .x = low half
    return *reinterpret_cast<uint32_t*>(&h);
}
// m16n8k16 row.col bf16 -> f32 accum (sm_80+ baseline PTX; HMMA on sm_103)
__device__ __forceinline__ void mma16816(float& c0, float& c1, float& c2, float& c3,
                                         uint32_t a0, uint32_t a1, uint32_t a2, uint32_t a3,
                                         uint32_t b0, uint32_t b1) {
    asm("mma.sync.aligned.m16n8k16.row.col.f32.bf16.bf16.f32 "
        "{%0,%1,%2,%3}, {%4,%5,%6,%7}, {%8,%9}, {%0,%1,%2,%3};"
        : "+f"(c0), "+f"(c1), "+f"(c2), "+f"(c3)
        : "r"(a0), "r"(a1), "r"(a2), "r"(a3), "r"(b0), "r"(b1));
}

// ---------------------------------------------------------------------------
// Prep: pack codebook bf16 into B-fragment order.
// chunk i = ((tile*128 + g*4 + kc)*32 + lane); holds {B[k0],B[k0+1],B[k0+8],B[k0+9]}
// for code = tile*256 + g*8 + (lane>>2), k0 = kc*16 + (lane&3)*2.
// ---------------------------------------------------------------------------
__global__ void vq_prep_kernel(const float* __restrict__ emb) {
    int i = blockIdx.x * 256 + threadIdx.x;           // 131072 chunks
    int lane = i & 31, kc = (i >> 5) & 3, g = (i >> 7) & 31, tile = i >> 12;
    int gid = lane >> 2, tig = lane & 3;
    int code = tile * 256 + g * 8 + gid;
    int k0 = kc * 16 + tig * 2;
    const float* src = emb + (size_t)code * EMB_DIM;
    uint2 v;
    v.x = pack_bf2(src[k0],     src[k0 + 1]);
    v.y = pack_bf2(src[k0 + 8], src[k0 + 9]);
    reinterpret_cast<uint2*>(g_embB)[i] = v;
}

// ---------------------------------------------------------------------------
// Per-code norms: sequential fp32 adds (bit-matches reference)
// ---------------------------------------------------------------------------
__global__ void vq_enorm_kernel(const float* __restrict__ emb) {
    int c = blockIdx.x * blockDim.x + threadIdx.x;
    if (c < N_CODES) {
        const float* row = emb + (size_t)c * EMB_DIM;
        float s = 0.f;
#pragma unroll
        for (int k = 0; k < EMB_DIM; ++k) {
            float v = row[k];
            s = __fadd_rn(s, __fmul_rn(v, v));
        }
        g_enorm[c] = s;
    }
}

// ---------------------------------------------------------------------------
// Phase A: bf16 mma.sync filter. 512 CTAs x 256 threads (8 warps x 16 rows).
// Each warp: A frags for its 16 rows (K=64 => 4 k-chunks), loops 8192 codes in
// 256-code smem tiles (cp.async double-buffered). Per n8 group: 4 LDS.64 +
// 4 mma; epilogue keeps running max + margin candidates per (row, colgroup).
// ---------------------------------------------------------------------------
__global__ void __launch_bounds__(256, 2)
vq_phaseA_kernel(const float* __restrict__ z) {
    extern __shared__ char smem[];
    const int tid = threadIdx.x, lane = tid & 31, w = tid >> 5;
    const int gid = lane >> 2, tig = lane & 3;
    const int R0 = blockIdx.x * ROWS_PER_CTA + w * 16;
    const int rowA = R0 + gid, rowB = R0 + gid + 8;

    // A fragments (bf16) for rows rowA/rowB, 4 k-chunks
    uint32_t A[4][4];
    {
        const float2* zpA = (const float2*)(z + (size_t)rowA * EMB_DIM);
        const float2* zpB = (const float2*)(z + (size_t)rowB * EMB_DIM);
#pragma unroll
        for (int kc = 0; kc < 4; ++kc) {
            float2 v;
            v = zpA[kc * 8 + tig];     A[kc][0] = pack_bf2(v.x, v.y);
            v = zpB[kc * 8 + tig];     A[kc][1] = pack_bf2(v.x, v.y);
            v = zpA[kc * 8 + tig + 4]; A[kc][2] = pack_bf2(v.x, v.y);
            v = zpB[kc * 8 + tig + 4]; A[kc][3] = pack_bf2(v.x, v.y);
        }
    }

    const uint32_t sbase = smem_u32(smem);
    // prologue: tiles 0,1
#pragma unroll
    for (int t = 0; t < 2; ++t) {
#pragma unroll
        for (int j = 0; j < 8; ++j) {
            int chunk = tid + j * 256;
            cp_async16(sbase + (uint32_t)(t * TILE_B + chunk * 16),
                       (const char*)g_embB + (size_t)t * TILE_B + chunk * 16);
        }
        CP_COMMIT();
    }

    float rm0 = -CUDART_INF_F, rm1 = -CUDART_INF_F;
    float th0 = -CUDART_INF_F, th1 = -CUDART_INF_F;
    int n0 = 0, n1 = 0;
    const size_t l0 = ((size_t)rowA * 4 + tig) * CAP;
    const size_t l1 = ((size_t)rowB * 4 + tig) * CAP;

    for (int t = 0; t < NT; ++t) {
        CP_WAIT1();
        __syncthreads();
        const uint2* bp = (const uint2*)(smem + (t & 1) * TILE_B) + lane;
        const int tb = t * CT;

#pragma unroll 4
        for (int g = 0; g < 32; ++g) {
            uint2 b0 = bp[(g * 4 + 0) * 32];
            uint2 b1 = bp[(g * 4 + 1) * 32];
            uint2 b2 = bp[(g * 4 + 2) * 32];
            uint2 b3 = bp[(g * 4 + 3) * 32];
            float c0 = 0.f, c1 = 0.f, c2 = 0.f, c3 = 0.f;
            mma16816(c0, c1, c2, c3, A[0][0], A[0][1], A[0][2], A[0][3], b0.x, b0.y);
            mma16816(c0, c1, c2, c3, A[1][0], A[1][1], A[1][2], A[1][3], b1.x, b1.y);
            mma16816(c0, c1, c2, c3, A[2][0], A[2][1], A[2][2], A[2][3], b2.x, b2.y);
            mma16816(c0, c1, c2, c3, A[3][0], A[3][1], A[3][2], A[3][3], b3.x, b3.y);

            // epilogue: c0,c1 -> rowA cols {2tig,2tig+1}; c2,c3 -> rowB
            float m01 = fmaxf(c0, c1), m23 = fmaxf(c2, c3);
            if (m01 > th0) {                           // rare
                int cb = tb + g * 8 + 2 * tig;
                if (c0 > th0) { if (n0 < CAP) g_cand[l0 + n0] = cb;     ++n0; }
                if (c1 > th0) { if (n0 < CAP) g_cand[l0 + n0] = cb + 1; ++n0; }
                rm0 = fmaxf(rm0, m01); th0 = rm0 - MARGIN;
            }
            if (m23 > th1) {                           // rare
                int cb = tb + g * 8 + 2 * tig;
                if (c2 > th1) { if (n1 < CAP) g_cand[l1 + n1] = cb;     ++n1; }
                if (c3 > th1) { if (n1 < CAP) g_cand[l1 + n1] = cb + 1; ++n1; }
                rm1 = fmaxf(rm1, m23); th1 = rm1 - MARGIN;
            }
        }

        __syncthreads();                               // buffer (t&1) consumed
        if (t + 2 < NT) {
#pragma unroll
            for (int j = 0; j < 8; ++j) {
                int chunk = tid + j * 256;
                cp_async16(sbase + (uint32_t)((t & 1) * TILE_B + chunk * 16),
                           (const char*)g_embB + (size_t)(t + 2) * TILE_B + chunk * 16);
            }
        }
        CP_COMMIT();                                   // keep group-count invariant
    }
    g_ccnt[rowA * 4 + tig] = n0;
    g_ccnt[rowB * 4 + tig] = n1;
}

// ---------------------------------------------------------------------------
// Phase B: exact fp32 rescore (bit-identical chain to the passing round-3
// kernel: sequential fma dot k=0..63, d = fl(fl(a+b) - 2c), min-index ties).
// ---------------------------------------------------------------------------
__global__ void __launch_bounds__(128)
vq_phaseB_kernel(const float* __restrict__ z, const float* __restrict__ emb) {
    const int row = blockIdx.x * 128 + threadIdx.x;
    float zr[EMB_DIM];
    const float4* zp = (const float4*)(z + (size_t)row * EMB_DIM);
#pragma unroll
    for (int i = 0; i < 16; ++i) {
        float4 v = zp[i];
        zr[4 * i] = v.x; zr[4 * i + 1] = v.y; zr[4 * i + 2] = v.z; zr[4 * i + 3] = v.w;
    }
    float a = 0.f;
#pragma unroll
    for (int k = 0; k < EMB_DIM; ++k) a = __fadd_rn(a, __fmul_rn(zr[k], zr[k]));

    int cnt[4];
    bool ovf = false;
#pragma unroll
    for (int tg = 0; tg < 4; ++tg) {
        cnt[tg] = g_ccnt[row * 4 + tg];
        if (cnt[tg] > CAP) ovf = true;
    }

    float bestd = CUDART_INF_F;
    int   bestidx = 0x7fffffff;

    if (!ovf) {
#pragma unroll
        for (int tg = 0; tg < 4; ++tg) {
            const size_t base = ((size_t)row * 4 + tg) * CAP;
            for (int s = 0; s < cnt[tg]; ++s) {
                int j = g_cand[base + s];
                float dot = 0.f;
                const float4* ep = (const float4*)(emb + (size_t)j * EMB_DIM);
#pragma unroll
                for (int i = 0; i < 16; ++i) {
                    float4 e = ep[i];
                    dot = fmaf(zr[4 * i],     e.x, dot);
                    dot = fmaf(zr[4 * i + 1], e.y, dot);
                    dot = fmaf(zr[4 * i + 2], e.z, dot);
                    dot = fmaf(zr[4 * i + 3], e.w, dot);
                }
                float d = fmaf(-2.f, dot, __fadd_rn(a, g_enorm[j]));
                if (d < bestd || (d == bestd && j < bestidx)) { bestd = d; bestidx = j; }
            }
        }
    } else {
        for (int j = 0; j < N_CODES; ++j) {   // ascending: strict < = first-index
            float dot = 0.f;
            const float4* ep = (const float4*)(emb + (size_t)j * EMB_DIM);
#pragma unroll
            for (int i = 0; i < 16; ++i) {
                float4 e = ep[i];
                dot = fmaf(zr[4 * i],     e.x, dot);
                dot = fmaf(zr[4 * i + 1], e.y, dot);
                dot = fmaf(zr[4 * i + 2], e.z, dot);
                dot = fmaf(zr[4 * i + 3], e.w, dot);
            }
            float d = fmaf(-2.f, dot, __fadd_rn(a, g_enorm[j]));
            if (d < bestd) { bestd = d; bestidx = j; }
        }
    }
    g_idx_buf[row] = bestidx;
}

// ---------------------------------------------------------------------------
// Phase C: z_q gather + per-block loss partial — op/order-identical to round 3
// ---------------------------------------------------------------------------
__global__ void __launch_bounds__(256)
vq_zqloss_kernel(const float* __restrict__ z, const float* __restrict__ emb,
                 float* __restrict__ zq) {
    __shared__ int   idx_s[64];
    __shared__ float red_s[256];
    const int tid = threadIdx.x;
    const long row0 = (long)blockIdx.x * 64;
    if (tid < 64) idx_s[tid] = g_idx_buf[row0 + tid];
    __syncthreads();
    float lsum = 0.f;
    for (int i = tid; i < 64 * EMB_DIM; i += 256) {
        int r = i >> 6, k = i & 63;
        float e = emb[(size_t)idx_s[r] * EMB_DIM + k];
        float diff = e - z[(row0 + r) * EMB_DIM + k];
        lsum = fmaf(diff, diff, lsum);
        zq[(row0 + r) * EMB_DIM + k] = e;
    }
    red_s[tid] = lsum;
    __syncthreads();
#pragma unroll
    for (int s = 128; s > 0; s >>= 1) {
        if (tid < s) red_s[tid] += red_s[tid + s];
        __syncthreads();
    }
    if (tid == 0) g_partials[blockIdx.x] = red_s[0];
}

// ---------------------------------------------------------------------------
__global__ void vq_loss_kernel(float* __restrict__ out, int loss_off) {
    __shared__ float red_s[256];
    const int tid = threadIdx.x;
    float s = 0.f;
#pragma unroll
    for (int j = 0; j < LB / 256; ++j) s += g_partials[tid + j * 256];
    red_s[tid] = s;
    __syncthreads();
#pragma unroll
    for (int st = 128; st > 0; st >>= 1) {
        if (tid < st) red_s[tid] += red_s[tid + st];
        __syncthreads();
    }
    if (tid == 0 && loss_off >= 0)
        out[loss_off] = (1.0f + BETA) * (red_s[0] / (float)NZ_ELEMS);
}

__global__ void vq_idx_kernel(float* __restrict__ out_idx) {
    int i = blockIdx.x * blockDim.x + threadIdx.x;
    if (i < N_ROWS) out_idx[i] = (float)g_idx_buf[i];
}

// ---------------------------------------------------------------------------
extern "C" void kernel_launch(void* const* d_in, const int* in_sizes, int n_in,
                              void* d_out, int out_size) {
    const float* z   = (const float*)d_in[0];
    const float* emb = (const float*)d_in[1];
    float* out = (float*)d_out;

    const int smA = 2 * TILE_B;   // 64KB
    cudaFuncSetAttribute(vq_phaseA_kernel,
                         cudaFuncAttributeMaxDynamicSharedMemorySize, smA);

    vq_prep_kernel<<<512, 256>>>(emb);
    vq_enorm_kernel<<<(N_CODES + 255) / 256, 256>>>(emb);
    vq_phaseA_kernel<<<A_CTAS, 256, smA>>>(z);
    vq_phaseB_kernel<<<N_ROWS / 128, 128>>>(z, emb);
    vq_zqloss_kernel<<<LB, 256>>>(z, emb, out);

    long loss_off = -1, idx_off = -1;
    if (out_size >= NZ_ELEMS + 1 + N_ROWS) {        // z_q, loss, idx
        loss_off = NZ_ELEMS; idx_off = NZ_ELEMS + 1;
    } else if (out_size == NZ_ELEMS + N_ROWS) {     // z_q, idx
        idx_off = NZ_ELEMS;
    } else if (out_size == NZ_ELEMS + 1) {          // z_q, loss
        loss_off = NZ_ELEMS;
    }

    vq_loss_kernel<<<1, 256>>>(out, (int)loss_off);
    if (idx_off >= 0)
        vq_idx_kernel<<<(N_ROWS + 255) / 256, 256>>>(out + idx_off);
}

// round 6
// speedup vs baseline: 1.0009x; 1.0009x over previous
#include <cuda_runtime.h>
#include <cuda_bf16.h>
#include <math_constants.h>
#include <cstdint>

// Problem constants
#define N_ROWS   65536
#define EMB_DIM  64
#define N_CODES  8192
#define NZ_ELEMS 4194304
#define BETA     0.25f

// Phase A (tensor filter) config
#define ROWS_PER_CTA 128
#define A_CTAS   (N_ROWS / ROWS_PER_CTA)    // 512
#define CT       256                         // codes per smem tile
#define NT       (N_CODES / CT)              // 32
#define TILE_B   32768                       // 256 codes * 64 k * 2B, frag-packed
#define MARGIN   1.5e-4f
#define CAP      32

#define LB       1024                        // loss partial blocks (64 rows each)

// ---------------- device scratch (no cudaMalloc allowed) -------------------
__device__ float g_enorm[N_CODES];
__device__ __align__(16) __nv_bfloat16 g_embB[N_CODES * EMB_DIM]; // frag-packed
__device__ int   g_idx_buf[N_ROWS];
__device__ float g_partials[LB];
__device__ int   g_cand[(size_t)N_ROWS * 4 * CAP];
__device__ int   g_ccnt[N_ROWS * 4];

// ---------------- helpers ---------------------------------------------------
__device__ __forceinline__ uint32_t smem_u32(const void* p) {
    uint32_t a;
    asm("{ .reg .u64 t; cvta.to.shared.u64 t, %1; cvt.u32.u64 %0, t; }"
        : "=r"(a) : "l"(p));
    return a;
}
__device__ __forceinline__ void cp_async16(uint32_t sm, const void* g) {
    asm volatile("cp.async.cg.shared.global [%0], [%1], 16;" :: "r"(sm), "l"(g));
}
#define CP_COMMIT() asm volatile("cp.async.commit_group;")
#define CP_WAIT1()  asm volatile("cp.async.wait_group 1;")

__device__ __forceinline__ uint32_t pack_bf2(float x, float y) {
    __nv_bfloat162 h = __floats2bfloat162_rn(x, y);   // .x = low half
    return *reinterpret_cast<uint32_t*>(&h);
}
// m16n8k16 row.col bf16 -> f32 accum (sm_80+ baseline PTX; HMMA on sm_103)
__device__ __forceinline__ void mma16816(float& c0, float& c1, float& c2, float& c3,
                                         uint32_t a0, uint32_t a1, uint32_t a2, uint32_t a3,
                                         uint32_t b0, uint32_t b1) {
    asm("mma.sync.aligned.m16n8k16.row.col.f32.bf16.bf16.f32 "
        "{%0,%1,%2,%3}, {%4,%5,%6,%7}, {%8,%9}, {%0,%1,%2,%3};"
        : "+f"(c0), "+f"(c1), "+f"(c2), "+f"(c3)
        : "r"(a0), "r"(a1), "r"(a2), "r"(a3), "r"(b0), "r"(b1));
}

// ---------------------------------------------------------------------------
// Prep: pack codebook bf16 into B-fragment order.
// chunk i = ((tile*128 + g*4 + kc)*32 + lane); holds {B[k0],B[k0+1],B[k0+8],B[k0+9]}
// for code = tile*256 + g*8 + (lane>>2), k0 = kc*16 + (lane&3)*2.
// ---------------------------------------------------------------------------
__global__ void vq_prep_kernel(const float* __restrict__ emb) {
    int i = blockIdx.x * 256 + threadIdx.x;           // 131072 chunks
    int lane = i & 31, kc = (i >> 5) & 3, g = (i >> 7) & 31, tile = i >> 12;
    int gid = lane >> 2, tig = lane & 3;
    int code = tile * 256 + g * 8 + gid;
    int k0 = kc * 16 + tig * 2;
    const float* src = emb + (size_t)code * EMB_DIM;
    uint2 v;
    v.x = pack_bf2(src[k0],     src[k0 + 1]);
    v.y = pack_bf2(src[k0 + 8], src[k0 + 9]);
    reinterpret_cast<uint2*>(g_embB)[i] = v;
}

// ---------------------------------------------------------------------------
// Per-code norms: sequential fp32 adds (bit-matches reference)
// ---------------------------------------------------------------------------
__global__ void vq_enorm_kernel(const float* __restrict__ emb) {
    int c = blockIdx.x * blockDim.x + threadIdx.x;
    if (c < N_CODES) {
        const float* row = emb + (size_t)c * EMB_DIM;
        float s = 0.f;
#pragma unroll
        for (int k = 0; k < EMB_DIM; ++k) {
            float v = row[k];
            s = __fadd_rn(s, __fmul_rn(v, v));
        }
        g_enorm[c] = s;
    }
}

// ---------------------------------------------------------------------------
// Phase A: bf16 mma.sync filter. 512 CTAs x 256 threads (8 warps x 16 rows).
// Each warp: A frags for its 16 rows (K=64 => 4 k-chunks), loops 8192 codes in
// 256-code smem tiles (cp.async double-buffered). Per n8 group: 4 LDS.64 +
// 4 mma; epilogue keeps running max + margin candidates per (row, colgroup).
// ---------------------------------------------------------------------------
__global__ void __launch_bounds__(256, 2)
vq_phaseA_kernel(const float* __restrict__ z) {
    extern __shared__ char smem[];
    const int tid = threadIdx.x, lane = tid & 31, w = tid >> 5;
    const int gid = lane >> 2, tig = lane & 3;
    const int R0 = blockIdx.x * ROWS_PER_CTA + w * 16;
    const int rowA = R0 + gid, rowB = R0 + gid + 8;

    // A fragments (bf16) for rows rowA/rowB, 4 k-chunks
    uint32_t A[4][4];
    {
        const float2* zpA = (const float2*)(z + (size_t)rowA * EMB_DIM);
        const float2* zpB = (const float2*)(z + (size_t)rowB * EMB_DIM);
#pragma unroll
        for (int kc = 0; kc < 4; ++kc) {
            float2 v;
            v = zpA[kc * 8 + tig];     A[kc][0] = pack_bf2(v.x, v.y);
            v = zpB[kc * 8 + tig];     A[kc][1] = pack_bf2(v.x, v.y);
            v = zpA[kc * 8 + tig + 4]; A[kc][2] = pack_bf2(v.x, v.y);
            v = zpB[kc * 8 + tig + 4]; A[kc][3] = pack_bf2(v.x, v.y);
        }
    }

    const uint32_t sbase = smem_u32(smem);
    // prologue: tiles 0,1
#pragma unroll
    for (int t = 0; t < 2; ++t) {
#pragma unroll
        for (int j = 0; j < 8; ++j) {
            int chunk = tid + j * 256;
            cp_async16(sbase + (uint32_t)(t * TILE_B + chunk * 16),
                       (const char*)g_embB + (size_t)t * TILE_B + chunk * 16);
        }
        CP_COMMIT();
    }

    float rm0 = -CUDART_INF_F, rm1 = -CUDART_INF_F;
    float th0 = -CUDART_INF_F, th1 = -CUDART_INF_F;
    int n0 = 0, n1 = 0;
    const size_t l0 = ((size_t)rowA * 4 + tig) * CAP;
    const size_t l1 = ((size_t)rowB * 4 + tig) * CAP;

    for (int t = 0; t < NT; ++t) {
        CP_WAIT1();
        __syncthreads();
        const uint2* bp = (const uint2*)(smem + (t & 1) * TILE_B) + lane;
        const int tb = t * CT;

#pragma unroll 4
        for (int g = 0; g < 32; ++g) {
            uint2 b0 = bp[(g * 4 + 0) * 32];
            uint2 b1 = bp[(g * 4 + 1) * 32];
            uint2 b2 = bp[(g * 4 + 2) * 32];
            uint2 b3 = bp[(g * 4 + 3) * 32];
            float c0 = 0.f, c1 = 0.f, c2 = 0.f, c3 = 0.f;
            mma16816(c0, c1, c2, c3, A[0][0], A[0][1], A[0][2], A[0][3], b0.x, b0.y);
            mma16816(c0, c1, c2, c3, A[1][0], A[1][1], A[1][2], A[1][3], b1.x, b1.y);
            mma16816(c0, c1, c2, c3, A[2][0], A[2][1], A[2][2], A[2][3], b2.x, b2.y);
            mma16816(c0, c1, c2, c3, A[3][0], A[3][1], A[3][2], A[3][3], b3.x, b3.y);

            // epilogue: c0,c1 -> rowA cols {2tig,2tig+1}; c2,c3 -> rowB
            float m01 = fmaxf(c0, c1), m23 = fmaxf(c2, c3);
            if (m01 > th0) {                           // rare
                int cb = tb + g * 8 + 2 * tig;
                if (c0 > th0) { if (n0 < CAP) g_cand[l0 + n0] = cb;     ++n0; }
                if (c1 > th0) { if (n0 < CAP) g_cand[l0 + n0] = cb + 1; ++n0; }
                rm0 = fmaxf(rm0, m01); th0 = rm0 - MARGIN;
            }
            if (m23 > th1) {                           // rare
                int cb = tb + g * 8 + 2 * tig;
                if (c2 > th1) { if (n1 < CAP) g_cand[l1 + n1] = cb;     ++n1; }
                if (c3 > th1) { if (n1 < CAP) g_cand[l1 + n1] = cb + 1; ++n1; }
                rm1 = fmaxf(rm1, m23); th1 = rm1 - MARGIN;
            }
        }

        __syncthreads();                               // buffer (t&1) consumed
        if (t + 2 < NT) {
#pragma unroll
            for (int j = 0; j < 8; ++j) {
                int chunk = tid + j * 256;
                cp_async16(sbase + (uint32_t)((t & 1) * TILE_B + chunk * 16),
                           (const char*)g_embB + (size_t)(t + 2) * TILE_B + chunk * 16);
            }
        }
        CP_COMMIT();                                   // keep group-count invariant
    }
    g_ccnt[rowA * 4 + tig] = n0;
    g_ccnt[rowB * 4 + tig] = n1;
}

// ---------------------------------------------------------------------------
// Phase B: exact fp32 rescore (bit-identical chain to the passing round-3
// kernel: sequential fma dot k=0..63, d = fl(fl(a+b) - 2c), min-index ties).
// ---------------------------------------------------------------------------
__global__ void __launch_bounds__(128)
vq_phaseB_kernel(const float* __restrict__ z, const float* __restrict__ emb) {
    const int row = blockIdx.x * 128 + threadIdx.x;
    float zr[EMB_DIM];
    const float4* zp = (const float4*)(z + (size_t)row * EMB_DIM);
#pragma unroll
    for (int i = 0; i < 16; ++i) {
        float4 v = zp[i];
        zr[4 * i] = v.x; zr[4 * i + 1] = v.y; zr[4 * i + 2] = v.z; zr[4 * i + 3] = v.w;
    }
    float a = 0.f;
#pragma unroll
    for (int k = 0; k < EMB_DIM; ++k) a = __fadd_rn(a, __fmul_rn(zr[k], zr[k]));

    int cnt[4];
    bool ovf = false;
#pragma unroll
    for (int tg = 0; tg < 4; ++tg) {
        cnt[tg] = g_ccnt[row * 4 + tg];
        if (cnt[tg] > CAP) ovf = true;
    }

    float bestd = CUDART_INF_F;
    int   bestidx = 0x7fffffff;

    if (!ovf) {
#pragma unroll
        for (int tg = 0; tg < 4; ++tg) {
            const size_t base = ((size_t)row * 4 + tg) * CAP;
            for (int s = 0; s < cnt[tg]; ++s) {
                int j = g_cand[base + s];
                float dot = 0.f;
                const float4* ep = (const float4*)(emb + (size_t)j * EMB_DIM);
#pragma unroll
                for (int i = 0; i < 16; ++i) {
                    float4 e = ep[i];
                    dot = fmaf(zr[4 * i],     e.x, dot);
                    dot = fmaf(zr[4 * i + 1], e.y, dot);
                    dot = fmaf(zr[4 * i + 2], e.z, dot);
                    dot = fmaf(zr[4 * i + 3], e.w, dot);
                }
                float d = fmaf(-2.f, dot, __fadd_rn(a, g_enorm[j]));
                if (d < bestd || (d == bestd && j < bestidx)) { bestd = d; bestidx = j; }
            }
        }
    } else {
        for (int j = 0; j < N_CODES; ++j) {   // ascending: strict < = first-index
            float dot = 0.f;
            const float4* ep = (const float4*)(emb + (size_t)j * EMB_DIM);
#pragma unroll
            for (int i = 0; i < 16; ++i) {
                float4 e = ep[i];
                dot = fmaf(zr[4 * i],     e.x, dot);
                dot = fmaf(zr[4 * i + 1], e.y, dot);
                dot = fmaf(zr[4 * i + 2], e.z, dot);
                dot = fmaf(zr[4 * i + 3], e.w, dot);
            }
            float d = fmaf(-2.f, dot, __fadd_rn(a, g_enorm[j]));
            if (d < bestd) { bestd = d; bestidx = j; }
        }
    }
    g_idx_buf[row] = bestidx;
}

// ---------------------------------------------------------------------------
// Phase C: z_q gather + per-block loss partial — op/order-identical to round 3
// ---------------------------------------------------------------------------
__global__ void __launch_bounds__(256)
vq_zqloss_kernel(const float* __restrict__ z, const float* __restrict__ emb,
                 float* __restrict__ zq) {
    __shared__ int   idx_s[64];
    __shared__ float red_s[256];
    const int tid = threadIdx.x;
    const long row0 = (long)blockIdx.x * 64;
    if (tid < 64) idx_s[tid] = g_idx_buf[row0 + tid];
    __syncthreads();
    float lsum = 0.f;
    for (int i = tid; i < 64 * EMB_DIM; i += 256) {
        int r = i >> 6, k = i & 63;
        float e = emb[(size_t)idx_s[r] * EMB_DIM + k];
        float diff = e - z[(row0 + r) * EMB_DIM + k];
        lsum = fmaf(diff, diff, lsum);
        zq[(row0 + r) * EMB_DIM + k] = e;
    }
    red_s[tid] = lsum;
    __syncthreads();
#pragma unroll
    for (int s = 128; s > 0; s >>= 1) {
        if (tid < s) red_s[tid] += red_s[tid + s];
        __syncthreads();
    }
    if (tid == 0) g_partials[blockIdx.x] = red_s[0];
}

// ---------------------------------------------------------------------------
__global__ void vq_loss_kernel(float* __restrict__ out, int loss_off) {
    __shared__ float red_s[256];
    const int tid = threadIdx.x;
    float s = 0.f;
#pragma unroll
    for (int j = 0; j < LB / 256; ++j) s += g_partials[tid + j * 256];
    red_s[tid] = s;
    __syncthreads();
#pragma unroll
    for (int st = 128; st > 0; st >>= 1) {
        if (tid < st) red_s[tid] += red_s[tid + st];
        __syncthreads();
    }
    if (tid == 0 && loss_off >= 0)
        out[loss_off] = (1.0f + BETA) * (red_s[0] / (float)NZ_ELEMS);
}

__global__ void vq_idx_kernel(float* __restrict__ out_idx) {
    int i = blockIdx.x * blockDim.x + threadIdx.x;
    if (i < N_ROWS) out_idx[i] = (float)g_idx_buf[i];
}

// ---------------------------------------------------------------------------
extern "C" void kernel_launch(void* const* d_in, const int* in_sizes, int n_in,
                              void* d_out, int out_size) {
    const float* z   = (const float*)d_in[0];
    const float* emb = (const float*)d_in[1];
    float* out = (float*)d_out;

    const int smA = 2 * TILE_B;   // 64KB
    cudaFuncSetAttribute(vq_phaseA_kernel,
                         cudaFuncAttributeMaxDynamicSharedMemorySize, smA);

    vq_prep_kernel<<<512, 256>>>(emb);
    vq_enorm_kernel<<<(N_CODES + 255) / 256, 256>>>(emb);
    vq_phaseA_kernel<<<A_CTAS, 256, smA>>>(z);
    vq_phaseB_kernel<<<N_ROWS / 128, 128>>>(z, emb);
    vq_zqloss_kernel<<<LB, 256>>>(z, emb, out);

    long loss_off = -1, idx_off = -1;
    if (out_size >= NZ_ELEMS + 1 + N_ROWS) {        // z_q, loss, idx
        loss_off = NZ_ELEMS; idx_off = NZ_ELEMS + 1;
    } else if (out_size == NZ_ELEMS + N_ROWS) {     // z_q, idx
        idx_off = NZ_ELEMS;
    } else if (out_size == NZ_ELEMS + 1) {          // z_q, loss
        loss_off = NZ_ELEMS;
    }

    vq_loss_kernel<<<1, 256>>>(out, (int)loss_off);
    if (idx_off >= 0)
        vq_idx_kernel<<<(N_ROWS + 255) / 256, 256>>>(out + idx_off);
}